// round 1
// baseline (speedup 1.0000x reference)
#include <cuda_runtime.h>

// hidden_states: [B=32, S=4096, H=768] fp32
// w_start, w_end: [768] fp32
// out: [2, B*S] fp32  (start_logits then end_logits)

static constexpr int H = 768;
static constexpr int H_VEC = H / 4;           // 192 float4 per row
static constexpr int VEC_PER_LANE = H_VEC / 32; // 6

__global__ __launch_bounds__(256, 8)
void dual_dot_kernel(const float* __restrict__ hs,
                     const float* __restrict__ w_start,
                     const float* __restrict__ w_end,
                     float* __restrict__ out,
                     int rows) {
    const int warp = (int)((blockIdx.x * blockDim.x + threadIdx.x) >> 5);
    const int lane = threadIdx.x & 31;
    if (warp >= rows) return;

    const float4* __restrict__ row = reinterpret_cast<const float4*>(hs) + (size_t)warp * H_VEC;
    const float4* __restrict__ ws  = reinterpret_cast<const float4*>(w_start);
    const float4* __restrict__ we  = reinterpret_cast<const float4*>(w_end);

    float s = 0.0f, e = 0.0f;
    #pragma unroll
    for (int j = 0; j < VEC_PER_LANE; ++j) {
        const int idx = lane + 32 * j;
        float4 hv = row[idx];
        float4 a  = ws[idx];
        float4 b  = we[idx];
        s = fmaf(hv.x, a.x, s); s = fmaf(hv.y, a.y, s);
        s = fmaf(hv.z, a.z, s); s = fmaf(hv.w, a.w, s);
        e = fmaf(hv.x, b.x, e); e = fmaf(hv.y, b.y, e);
        e = fmaf(hv.z, b.z, e); e = fmaf(hv.w, b.w, e);
    }

    #pragma unroll
    for (int o = 16; o > 0; o >>= 1) {
        s += __shfl_xor_sync(0xffffffffu, s, o);
        e += __shfl_xor_sync(0xffffffffu, e, o);
    }

    if (lane == 0) {
        out[warp]        = s;   // start_logits
        out[rows + warp] = e;   // end_logits
    }
}

extern "C" void kernel_launch(void* const* d_in, const int* in_sizes, int n_in,
                              void* d_out, int out_size) {
    const float* hs      = (const float*)d_in[0];
    const float* w_start = (const float*)d_in[1];
    const float* w_end   = (const float*)d_in[2];
    float* out           = (float*)d_out;

    const int rows = in_sizes[0] / H;           // 32*4096 = 131072
    const int threads = 256;                    // 8 warps/block
    const int warps_per_block = threads / 32;
    const int blocks = (rows + warps_per_block - 1) / warps_per_block;

    dual_dot_kernel<<<blocks, threads>>>(hs, w_start, w_end, out, rows);
}